// round 10
// baseline (speedup 1.0000x reference)
#include <cuda_runtime.h>
#include <cuda_bf16.h>
#include <math.h>
#include <stdint.h>

#define Bsz   1024
#define TENC  64
#define SEG   32
#define Hdim  512
#define FOURH 2048
#define BH    (Bsz * Hdim)

#if defined(__CUDA_ARCH__) && (defined(__CUDA_ARCH_FEAT_SM103_ALL) || \
    defined(__CUDA_ARCH_FEAT_SM100_ALL) || defined(__CUDA_ARCH_SPECIFIC__) || \
    defined(__CUDA_ARCH_FAMILY_SPECIFIC__))
#define TC_OK 1
#else
#define TC_OK 0
#endif

// ------------------------- static scratch -------------------------
__device__ __nv_bfloat16 g_h0hi[(size_t)97 * BH];
__device__ __nv_bfloat16 g_h0lo[(size_t)97 * BH];
__device__ __nv_bfloat16 g_h1hi[(size_t)97 * BH];
__device__ __nv_bfloat16 g_h1lo[(size_t)97 * BH];
__device__ float g_c0[BH];
__device__ float g_c1[BH];
__device__ __nv_bfloat16 g_xhi[(size_t)65536 * 128];
__device__ __nv_bfloat16 g_xlo[(size_t)65536 * 128];
__device__ __nv_bfloat16 g_eU0h[(size_t)2048 * 512], g_eU0l[(size_t)2048 * 512];
__device__ __nv_bfloat16 g_eU1h[(size_t)2048 * 512], g_eU1l[(size_t)2048 * 512];
__device__ __nv_bfloat16 g_dU0h[(size_t)2048 * 512], g_dU0l[(size_t)2048 * 512];
__device__ __nv_bfloat16 g_dU1h[(size_t)2048 * 512], g_dU1l[(size_t)2048 * 512];
__device__ __nv_bfloat16 g_eW1h[(size_t)2048 * 512], g_eW1l[(size_t)2048 * 512];
__device__ __nv_bfloat16 g_dW1h[(size_t)2048 * 512], g_dW1l[(size_t)2048 * 512];
__device__ __nv_bfloat16 g_eW0h[(size_t)2048 * 128], g_eW0l[(size_t)2048 * 128];

struct Job {
    const __nv_bfloat16 *A1h, *A1l, *B1h, *B1l;   // K = kA1
    const __nv_bfloat16 *A2h, *A2l, *B2h, *B2l;   // optional K-segment (kA2)
    const float *bias, *dec, *dW0;
    float *c_state;
    __nv_bfloat16 *ohi, *olo;
    int kA1, kA2, active;
};

// ------------------------- helpers -------------------------
__device__ __forceinline__ uint32_t smem_to_u32(const void* p) {
    uint32_t a;
    asm("{ .reg .u64 t; cvta.to.shared.u64 t, %1; cvt.u32.u64 %0, t; }" : "=r"(a) : "l"(p));
    return a;
}
__device__ __forceinline__ void lstm_gates(float zi, float zf, float zg, float zo,
                                           float cold, float& cn, float& h) {
    float ig = 1.f / (1.f + expf(-zi));
    float fg = 1.f / (1.f + expf(-zf));
    float gg = tanhf(zg);
    float og = 1.f / (1.f + expf(-zo));
    cn = fg * cold + ig * gg;
    h  = og * tanhf(cn);
}

#if TC_OK
__device__ __forceinline__ uint32_t elect_one_pred() {
    uint32_t pred;
    asm volatile("{\n\t.reg .pred p;\n\telect.sync _|p, 0xFFFFFFFF;\n\t"
                 "selp.b32 %0, 1, 0, p;\n\t}" : "=r"(pred));
    return pred;
}
#define TCGEN05_ALLOC(addr, n) \
    asm volatile("tcgen05.alloc.cta_group::1.sync.aligned.shared::cta.b32 [%0], %1;" \
                 :: "r"((uint32_t)(addr)), "r"((uint32_t)(n)) : "memory")
#define TCGEN05_DEALLOC(tm, n) \
    asm volatile("tcgen05.dealloc.cta_group::1.sync.aligned.b32 %0, %1;" :: "r"(tm), "r"((uint32_t)(n)))
#define TCGEN05_RELINQ() \
    asm volatile("tcgen05.relinquish_alloc_permit.cta_group::1.sync.aligned;")
#define TCGEN05_COMMIT(mb) \
    asm volatile("tcgen05.commit.cta_group::1.mbarrier::arrive::one.shared::cluster.b64 [%0];" \
                 :: "r"((uint32_t)(mb)) : "memory")
#define TCGEN05_WAIT_LD() asm volatile("tcgen05.wait::ld.sync.aligned;" ::: "memory")
#define TCGEN05_FENCE_AFTER() asm volatile("tcgen05.fence::after_thread_sync;" ::: "memory")
#define MBARRIER_INIT(mb, cnt) \
    asm volatile("mbarrier.init.shared.b64 [%0], %1;" :: "r"((uint32_t)(mb)), "r"((uint32_t)(cnt)) : "memory")
#define FENCE_PROXY_ASYNC() asm volatile("fence.proxy.async.shared::cta;" ::: "memory")
#define CP_ASYNC16(dst, src) \
    asm volatile("cp.async.cg.shared.global [%0], [%1], 16;" :: "r"((uint32_t)(dst)), "l"(src) : "memory")
// NOTE: .noinc is load-bearing — the default variant pre-increments the pending
// count and never consumes the init count (round-9 deadlock).
#define CP_MBAR_ARRIVE_NOINC(mb) \
    asm volatile("cp.async.mbarrier.arrive.noinc.shared.b64 [%0];" :: "r"((uint32_t)(mb)) : "memory")

#define MBARRIER_WAIT_PARITY(mb, par) do { \
    uint32_t _m = (uint32_t)(mb), _p = (uint32_t)(par), _d; \
    asm volatile("{\n\t.reg .pred p;\n\t" \
        "mbarrier.try_wait.parity.acquire.cta.shared::cta.b64 p, [%1], %2;\n\t" \
        "selp.b32 %0, 1, 0, p;\n\t}" : "=r"(_d) : "r"(_m), "r"(_p) : "memory"); \
    if (!_d) { \
        asm volatile("{\n\t.reg .pred P1;\n\t" \
            "WL_%=:\n\t" \
            "mbarrier.try_wait.parity.acquire.cta.shared::cta.b64 P1, [%0], %1, 0x989680;\n\t" \
            "@P1 bra.uni WD_%=;\n\tbra.uni WL_%=;\n\tWD_%=:\n\t}" \
            :: "r"(_m), "r"(_p) : "memory"); \
    } \
} while (0)

#define TCGEN05_LD_32X32B_X32(r, ta) \
    asm volatile("tcgen05.ld.sync.aligned.32x32b.x32.b32 " \
        "{%0, %1, %2, %3, %4, %5, %6, %7, %8, %9, %10, %11, %12, %13, %14, %15, " \
        " %16, %17, %18, %19, %20, %21, %22, %23, %24, %25, %26, %27, %28, %29, %30, %31}, [%32];" \
        : "=r"((r)[0]), "=r"((r)[1]), "=r"((r)[2]), "=r"((r)[3]), "=r"((r)[4]), "=r"((r)[5]), \
          "=r"((r)[6]), "=r"((r)[7]), "=r"((r)[8]), "=r"((r)[9]), "=r"((r)[10]), "=r"((r)[11]), \
          "=r"((r)[12]), "=r"((r)[13]), "=r"((r)[14]), "=r"((r)[15]), "=r"((r)[16]), "=r"((r)[17]), \
          "=r"((r)[18]), "=r"((r)[19]), "=r"((r)[20]), "=r"((r)[21]), "=r"((r)[22]), "=r"((r)[23]), \
          "=r"((r)[24]), "=r"((r)[25]), "=r"((r)[26]), "=r"((r)[27]), "=r"((r)[28]), "=r"((r)[29]), \
          "=r"((r)[30]), "=r"((r)[31]) : "r"(ta))

static constexpr uint64_t SMEM_DESC_BASE_SW128 =
    (uint64_t(2) << 61) | (uint64_t(1) << 46) | (uint64_t(64) << 32) | (uint64_t(1) << 16);
#define MAKE_SMEM_DESC(a) (SMEM_DESC_BASE_SW128 | ((uint64_t)((a) >> 4) & 0x3FFF))
#define MMA_IDESC 0x8200490u   // F32 acc, bf16 x bf16, M=128, N=128

__device__ __forceinline__ void mma_f16_ss(uint32_t d, uint64_t a, uint64_t b, bool acc) {
    uint32_t en = acc ? 1u : 0u;
    asm volatile("{\n\t.reg .pred p;\n\tsetp.ne.u32 p, %5, 0;\n\t"
        "tcgen05.mma.cta_group::1.kind::f16 [%0], %1, %2, %3, {%4, %4, %4, %4}, p;\n\t}"
        :: "r"(d), "l"(a), "l"(b), "r"(MMA_IDESC), "r"(0u), "r"(en) : "memory");
}
#endif // TC_OK

// ------------------- fused conversion (1 launch) -------------------
#define WK (2048 * 512)
__global__ void __launch_bounds__(256) conv_all(
    const float* __restrict__ eU0, const float* __restrict__ eU1,
    const float* __restrict__ dU0, const float* __restrict__ dU1,
    const float* __restrict__ eW1, const float* __restrict__ dW1,
    const float* __restrict__ eW0, const float* __restrict__ x,
    __nv_bfloat16* eU0h, __nv_bfloat16* eU0l, __nv_bfloat16* eU1h, __nv_bfloat16* eU1l,
    __nv_bfloat16* dU0h, __nv_bfloat16* dU0l, __nv_bfloat16* dU1h, __nv_bfloat16* dU1l,
    __nv_bfloat16* eW1h, __nv_bfloat16* eW1l, __nv_bfloat16* dW1h, __nv_bfloat16* dW1l,
    __nv_bfloat16* eW0h, __nv_bfloat16* eW0l, __nv_bfloat16* xh, __nv_bfloat16* xl)
{
    size_t idx = (size_t)blockIdx.x * 256 + threadIdx.x;
    const size_t seg6 = (size_t)6 * WK;
    const size_t seg7 = seg6 + 2048 * 128;
    const size_t segE = seg7 + (size_t)65536 * 128;
    if (idx >= segE) return;
    if (idx < seg6) {
        int which = (int)(idx / WK), wk = (int)(idx % WK);
        int n = wk / 512, k = wk % 512;
        int r = n & 127, hT = n >> 7;
        int orig = (r & 3) * 512 + hT * 32 + (r >> 2);
        const float* s = (which == 0) ? eU0 : (which == 1) ? eU1 : (which == 2) ? dU0
                        : (which == 3) ? dU1 : (which == 4) ? eW1 : dW1;
        __nv_bfloat16* dh = (which == 0) ? eU0h : (which == 1) ? eU1h : (which == 2) ? dU0h
                           : (which == 3) ? dU1h : (which == 4) ? eW1h : dW1h;
        __nv_bfloat16* dl = (which == 0) ? eU0l : (which == 1) ? eU1l : (which == 2) ? dU0l
                           : (which == 3) ? dU1l : (which == 4) ? eW1l : dW1l;
        float v = s[(size_t)k * FOURH + orig];
        __nv_bfloat16 h = __float2bfloat16(v);
        dh[wk] = h; dl[wk] = __float2bfloat16(v - __bfloat162float(h));
    } else if (idx < seg7) {
        int wk = (int)(idx - seg6);
        int n = wk / 128, k = wk % 128;
        int r = n & 127, hT = n >> 7;
        int orig = (r & 3) * 512 + hT * 32 + (r >> 2);
        float v = (k < 121) ? eW0[(size_t)k * FOURH + orig] : 0.f;
        __nv_bfloat16 h = __float2bfloat16(v);
        eW0h[wk] = h; eW0l[wk] = __float2bfloat16(v - __bfloat162float(h));
    } else {
        size_t wk = idx - seg7;
        int m = (int)(wk >> 7), k = (int)(wk & 127);
        int t = m >> 10, b = m & 1023;
        float v = (k < 121) ? x[(size_t)b * (TENC * 121) + t * 121 + k] : 0.f;
        __nv_bfloat16 h = __float2bfloat16(v);
        xh[wk] = h; xl[wk] = __float2bfloat16(v - __bfloat162float(h));
    }
}

__global__ void __launch_bounds__(256) zero_init(
    __nv_bfloat16* h0h, __nv_bfloat16* h0l, __nv_bfloat16* h1h, __nv_bfloat16* h1l,
    float* c0, float* c1)
{
    int i = blockIdx.x * 256 + threadIdx.x;
    if (i >= BH) return;
    __nv_bfloat16 z = __float2bfloat16(0.f);
    h0h[i] = z; h0l[i] = z; h1h[i] = z; h1l[i] = z;
    c0[i] = 0.f; c1[i] = 0.f;
}

// ------------------- wavefront step kernel -------------------
// grid (8, 8, 2), 128 threads. warp0 = MMA issuer, warps 1-3 = loaders.
#define STAGE_BYTES 98304
#define SMEM_C_OFF  (1024 + 2 * STAGE_BYTES)            // 197632
#define SMEM_BYTES  (SMEM_C_OFF + 128 * 68 * 4)          // 232448

__global__ void __launch_bounds__(128) wave_step(Job j0, Job j1)
{
    const Job J = (blockIdx.z == 0) ? j0 : j1;
    if (!J.active) return;

    extern __shared__ char smem[];
    const uint32_t sb = smem_to_u32(smem);
    const uint32_t tb = (sb + 1023u) & ~1023u;
    char* smemc = smem + (tb - sb);

    const int tid = threadIdx.x;
    const int nb = blockIdx.x;
    const size_t rowBase = (size_t)blockIdx.y * 128;
    const size_t colBase = (size_t)nb * 256;
    const int ch1 = J.kA1 >> 6;
    const int nch = ch1 + (J.A2h ? (J.kA2 >> 6) : 0);

#if TC_OK
    // barriers: full0 tb+8 (96), full1 tb+16 (96), done0 tb+24 (1), done1 tb+32 (1),
    //           MBF tb+40 (1), CBAR tb+48 (96)
    if (tid < 32) { TCGEN05_ALLOC(tb, 256); TCGEN05_RELINQ(); }
    if (tid == 0) {
        MBARRIER_INIT(tb + 8, 96);
        MBARRIER_INIT(tb + 16, 96);
        MBARRIER_INIT(tb + 24, 1);
        MBARRIER_INIT(tb + 32, 1);
        MBARRIER_INIT(tb + 40, 1);
        MBARRIER_INIT(tb + 48, 96);
    }
    __syncthreads();
    uint32_t tmem;
    asm volatile("ld.shared.b32 %0, [%1];" : "=r"(tmem) : "r"(tb));

    if (tid >= 32) {
        // ---------------- loader warps (96 threads) ----------------
        const int lid = tid - 32;
        // preload c tile (128 x 64 fp32 -> [128][68] padded)
        for (int i = lid; i < 2048; i += 96) {
            int r = i >> 4, q = i & 15;
            CP_ASYNC16(tb + SMEM_C_OFF + (uint32_t)(r * 272 + q * 16),
                       J.c_state + (rowBase + r) * Hdim + nb * 64 + q * 4);
        }
        CP_MBAR_ARRIVE_NOINC(tb + 48);

        for (int cc = 0; cc < nch; cc++) {
            if (cc >= 2)
                MBARRIER_WAIT_PARITY(tb + 24 + (uint32_t)(cc & 1) * 8, ((cc - 2) >> 1) & 1);
            const uint32_t st = tb + 1024 + (uint32_t)(cc & 1) * STAGE_BYTES;
            const __nv_bfloat16 *Ah, *Al, *Bh, *Bl;
            int kA, ko;
            if (cc < ch1) { Ah = J.A1h; Al = J.A1l; Bh = J.B1h; Bl = J.B1l; kA = J.kA1; ko = cc * 64; }
            else          { Ah = J.A2h; Al = J.A2l; Bh = J.B2h; Bl = J.B2l; kA = J.kA2; ko = (cc - ch1) * 64; }
#pragma unroll 8
            for (int i = lid; i < 6144; i += 96) {
                const __nv_bfloat16* src;
                uint32_t dst;
                if (i < 2048) {                      // A hi/lo: 128 rows x 128B each
                    int hi = (i < 1024);
                    int a = i & 1023;
                    int r = a >> 3, s = a & 7;
                    uint32_t off = (uint32_t)(r * 128 + s * 16);
                    off ^= (off >> 3) & 0x70;
                    dst = st + (hi ? 0u : 16384u) + off;
                    src = (hi ? Ah : Al) + (rowBase + r) * (size_t)kA + ko + s * 8;
                } else {                              // B hi/lo: 256 rows x 128B each
                    int t2 = i - 2048;
                    int hi = (t2 < 2048);
                    int a = t2 & 2047;
                    int r = a >> 3, s = a & 7;
                    uint32_t off = (uint32_t)(r * 128 + s * 16);
                    off ^= (off >> 3) & 0x70;
                    dst = st + 32768u + (hi ? 0u : 32768u) + off;
                    src = (hi ? Bh : Bl) + (colBase + r) * (size_t)kA + ko + s * 8;
                }
                CP_ASYNC16(dst, src);
            }
            CP_MBAR_ARRIVE_NOINC(tb + 8 + (uint32_t)(cc & 1) * 8);
        }
    } else {
        // ---------------- MMA warp ----------------
        if (elect_one_pred()) {
            for (int c = 0; c < nch; c++) {
                MBARRIER_WAIT_PARITY(tb + 8 + (uint32_t)(c & 1) * 8, (c >> 1) & 1);
                FENCE_PROXY_ASYNC();
                const uint32_t st = tb + 1024 + (uint32_t)(c & 1) * STAGE_BYTES;
                uint64_t adh = MAKE_SMEM_DESC(st);
                uint64_t adl = MAKE_SMEM_DESC(st + 16384);
                uint64_t bdh = MAKE_SMEM_DESC(st + 32768);
                uint64_t bdl = MAKE_SMEM_DESC(st + 65536);
#pragma unroll
                for (int term = 0; term < 3; term++) {
                    uint64_t ad = (term == 1) ? adl : adh;
                    uint64_t bd = (term == 2) ? bdl : bdh;
#pragma unroll
                    for (int j = 0; j < 4; j++) {
                        bool acc = !(c == 0 && term == 0 && j == 0);
                        mma_f16_ss(tmem,       ad + j * 2, bd + j * 2,        acc);
                        mma_f16_ss(tmem + 128, ad + j * 2, bd + 1024 + j * 2, acc);
                    }
                }
                TCGEN05_COMMIT(tb + 24 + (uint32_t)(c & 1) * 8);
            }
            TCGEN05_COMMIT(tb + 40);
        }
    }

    // ---------------- join + epilogue ----------------
    MBARRIER_WAIT_PARITY(tb + 40, 0);
    TCGEN05_FENCE_AFTER();
    MBARRIER_WAIT_PARITY(tb + 48, 0);

    float* scf = (float*)(smemc + SMEM_C_OFF);                     // [128][68]
    __nv_bfloat16* shi = (__nv_bfloat16*)(smemc + 1024);           // [128][66]
    __nv_bfloat16* slo = (__nv_bfloat16*)(smemc + 1024 + 16896);   // [128][66]

    const size_t row = rowBase + tid;
    const float dv = J.dec ? J.dec[row * SEG] : 0.f;

    for (int q = 0; q < 8; q++) {
        uint32_t dr[32];
        TCGEN05_LD_32X32B_X32(dr, tmem + q * 32);
        TCGEN05_WAIT_LD();
        const int nlb = ((q & 4) ? 32 : 0) + (q & 3) * 8;
#pragma unroll
        for (int jj = 0; jj < 8; jj++) {
            int nl = nlb + jj;
            int hg = nb * 64 + nl;
            float zi = __uint_as_float(dr[jj * 4 + 0]) + J.bias[hg];
            float zf = __uint_as_float(dr[jj * 4 + 1]) + J.bias[512 + hg];
            float zg = __uint_as_float(dr[jj * 4 + 2]) + J.bias[1024 + hg];
            float zo = __uint_as_float(dr[jj * 4 + 3]) + J.bias[1536 + hg];
            if (J.dec) {
                zi += dv * J.dW0[hg];
                zf += dv * J.dW0[512 + hg];
                zg += dv * J.dW0[1024 + hg];
                zo += dv * J.dW0[1536 + hg];
            }
            float cn, h;
            lstm_gates(zi, zf, zg, zo, scf[tid * 68 + nl], cn, h);
            scf[tid * 68 + nl] = cn;
            __nv_bfloat16 hh = __float2bfloat16(h);
            shi[tid * 66 + nl] = hh;
            slo[tid * 66 + nl] = __float2bfloat16(h - __bfloat162float(hh));
        }
    }
    __syncthreads();
#pragma unroll 4
    for (int i = 0; i < 64; i++) {
        int idx = i * 128 + tid, r = idx >> 6, cc = idx & 63;
        size_t o = (rowBase + r) * Hdim + nb * 64 + cc;
        J.c_state[o] = scf[r * 68 + cc];
        J.ohi[o] = shi[r * 66 + cc];
        J.olo[o] = slo[r * 66 + cc];
    }
    __syncthreads();
    if (tid < 32) TCGEN05_DEALLOC(tmem, 256);

#else
    // ---------- FFMA fallback (non-'a' pass; unused when 'a' cubin loads) ----------
    float* sA = (float*)(smemc + 1024);                // [32][132]
    float* sB = (float*)(smemc + 1024 + 16896);        // [32][68]
    const int tr = tid >> 3, tc8 = tid & 7;

    for (int pass = 0; pass < 4; pass++) {
        float acc[8][8];
#pragma unroll
        for (int r = 0; r < 8; r++)
#pragma unroll
            for (int j = 0; j < 8; j++) acc[r][j] = 0.f;

        for (int part = 0; part < 2; part++) {
            if (part == 1 && !J.A2h) break;
            const __nv_bfloat16* Ah = part ? J.A2h : J.A1h;
            const __nv_bfloat16* Al = part ? J.A2l : J.A1l;
            const __nv_bfloat16* Bh = part ? J.B2h : J.B1h;
            const __nv_bfloat16* Bl = part ? J.B2l : J.B1l;
            const int kA = part ? J.kA2 : J.kA1;
            for (int k0 = 0; k0 < kA; k0 += 32) {
                __syncthreads();
#pragma unroll 4
                for (int i = 0; i < 32; i++) {
                    int idx = i * 128 + tid, r = idx >> 5, kk = idx & 31;
                    size_t ao = (rowBase + r) * (size_t)kA + k0 + kk;
                    sA[kk * 132 + r] = __bfloat162float(Ah[ao]) + __bfloat162float(Al[ao]);
                }
#pragma unroll 2
                for (int i = 0; i < 16; i++) {
                    int idx = i * 128 + tid, r = idx >> 5, kk = idx & 31;
                    size_t bo = (colBase + pass * 64 + r) * (size_t)kA + k0 + kk;
                    sB[kk * 68 + r] = __bfloat162float(Bh[bo]) + __bfloat162float(Bl[bo]);
                }
                __syncthreads();
#pragma unroll
                for (int k = 0; k < 32; k++) {
                    float a[8], b[8];
#pragma unroll
                    for (int r = 0; r < 8; r++) a[r] = sA[k * 132 + tr * 8 + r];
#pragma unroll
                    for (int j = 0; j < 8; j++) b[j] = sB[k * 68 + tc8 * 8 + j];
#pragma unroll
                    for (int r = 0; r < 8; r++)
#pragma unroll
                        for (int j = 0; j < 8; j++) acc[r][j] += a[r] * b[j];
                }
            }
        }
        __syncthreads();
#pragma unroll
        for (int r = 0; r < 8; r++) {
            size_t row = rowBase + tr * 8 + r;
            float dvr = J.dec ? J.dec[row * SEG] : 0.f;
#pragma unroll
            for (int q = 0; q < 2; q++) {
                int nl = ((pass & 2) ? 32 : 0) + (pass & 1) * 16 + tc8 * 2 + q;
                int hg = nb * 64 + nl;
                float zi = acc[r][q * 4 + 0] + J.bias[hg];
                float zf = acc[r][q * 4 + 1] + J.bias[512 + hg];
                float zg = acc[r][q * 4 + 2] + J.bias[1024 + hg];
                float zo = acc[r][q * 4 + 3] + J.bias[1536 + hg];
                if (J.dec) {
                    zi += dvr * J.dW0[hg];
                    zf += dvr * J.dW0[512 + hg];
                    zg += dvr * J.dW0[1024 + hg];
                    zo += dvr * J.dW0[1536 + hg];
                }
                size_t o = row * Hdim + hg;
                float cn, h;
                lstm_gates(zi, zf, zg, zo, J.c_state[o], cn, h);
                J.c_state[o] = cn;
                __nv_bfloat16 hh = __float2bfloat16(h);
                J.ohi[o] = hh;
                J.olo[o] = __float2bfloat16(h - __bfloat162float(hh));
            }
        }
    }
#endif
}

// ------------------- final dense -------------------
__global__ void __launch_bounds__(256) dense_kernel(
    const __nv_bfloat16* __restrict__ hi, const __nv_bfloat16* __restrict__ lo,
    const float* __restrict__ W, const float* __restrict__ bb, float* __restrict__ out)
{
    int wid = (blockIdx.x * blockDim.x + threadIdx.x) >> 5;
    int lane = threadIdx.x & 31;
    if (wid >= Bsz * SEG) return;
    int b = wid / SEG, s = wid % SEG;
    size_t base = (size_t)(TENC + 1 + s) * BH + (size_t)b * Hdim;
    float sum = 0.f;
#pragma unroll 4
    for (int k = lane; k < Hdim; k += 32)
        sum += (__bfloat162float(hi[base + k]) + __bfloat162float(lo[base + k])) * W[k];
#pragma unroll
    for (int o = 16; o > 0; o >>= 1) sum += __shfl_down_sync(0xffffffffu, sum, o);
    if (lane == 0) out[(size_t)b * SEG + s] = sum + bb[0];
}

// ------------------- host -------------------
extern "C" void kernel_launch(void* const* d_in, const int* in_sizes, int n_in,
                              void* d_out, int out_size)
{
    const float* x      = (const float*)d_in[0];
    const float* decin  = (const float*)d_in[1];
    const float* eW0    = (const float*)d_in[2];
    const float* eU0    = (const float*)d_in[3];
    const float* eb0    = (const float*)d_in[4];
    const float* eW1    = (const float*)d_in[5];
    const float* eU1    = (const float*)d_in[6];
    const float* eb1    = (const float*)d_in[7];
    const float* dW0    = (const float*)d_in[8];
    const float* dU0    = (const float*)d_in[9];
    const float* db0    = (const float*)d_in[10];
    const float* dW1    = (const float*)d_in[11];
    const float* dU1    = (const float*)d_in[12];
    const float* db1    = (const float*)d_in[13];
    const float* denseW = (const float*)d_in[14];
    const float* denseb = (const float*)d_in[15];
    float* out = (float*)d_out;

    cudaFuncSetAttribute(wave_step, cudaFuncAttributeMaxDynamicSharedMemorySize, SMEM_BYTES);

    float *c0, *c1;
    __nv_bfloat16 *h0h, *h0l, *h1h, *h1l, *xh, *xl;
    __nv_bfloat16 *eU0h, *eU0l, *eU1h, *eU1l, *dU0h, *dU0l, *dU1h, *dU1l;
    __nv_bfloat16 *eW1h, *eW1l, *dW1h, *dW1l, *eW0h, *eW0l;
    cudaGetSymbolAddress((void**)&c0, g_c0);
    cudaGetSymbolAddress((void**)&c1, g_c1);
    cudaGetSymbolAddress((void**)&h0h, g_h0hi);
    cudaGetSymbolAddress((void**)&h0l, g_h0lo);
    cudaGetSymbolAddress((void**)&h1h, g_h1hi);
    cudaGetSymbolAddress((void**)&h1l, g_h1lo);
    cudaGetSymbolAddress((void**)&xh, g_xhi);
    cudaGetSymbolAddress((void**)&xl, g_xlo);
    cudaGetSymbolAddress((void**)&eU0h, g_eU0h); cudaGetSymbolAddress((void**)&eU0l, g_eU0l);
    cudaGetSymbolAddress((void**)&eU1h, g_eU1h); cudaGetSymbolAddress((void**)&eU1l, g_eU1l);
    cudaGetSymbolAddress((void**)&dU0h, g_dU0h); cudaGetSymbolAddress((void**)&dU0l, g_dU0l);
    cudaGetSymbolAddress((void**)&dU1h, g_dU1h); cudaGetSymbolAddress((void**)&dU1l, g_dU1l);
    cudaGetSymbolAddress((void**)&eW1h, g_eW1h); cudaGetSymbolAddress((void**)&eW1l, g_eW1l);
    cudaGetSymbolAddress((void**)&dW1h, g_dW1h); cudaGetSymbolAddress((void**)&dW1l, g_dW1l);
    cudaGetSymbolAddress((void**)&eW0h, g_eW0h); cudaGetSymbolAddress((void**)&eW0l, g_eW0l);

    {
        size_t total = (size_t)6 * WK + 2048 * 128 + (size_t)65536 * 128;
        conv_all<<<(int)((total + 255) / 256), 256>>>(
            eU0, eU1, dU0, dU1, eW1, dW1, eW0, x,
            eU0h, eU0l, eU1h, eU1l, dU0h, dU0l, dU1h, dU1l,
            eW1h, eW1l, dW1h, dW1l, eW0h, eW0l, xh, xl);
    }
    zero_init<<<(BH + 255) / 256, 256>>>(h0h, h0l, h1h, h1l, c0, c1);

    dim3 g(8, 8, 2);
    for (int w = 0; w <= 96; w++) {
        Job j0 = {}, j1 = {};
        if (w < 96) {                       // layer-0 step w
            int t = w;
            j0.active = 1;
            j0.kA1 = 512;
            j0.c_state = c0;
            if (t < TENC) {
                j0.A1h = h0h + (size_t)t * BH;  j0.A1l = h0l + (size_t)t * BH;
                j0.B1h = eU0h; j0.B1l = eU0l;
                j0.A2h = xh + (size_t)t * 1024 * 128;
                j0.A2l = xl + (size_t)t * 1024 * 128;
                j0.B2h = eW0h; j0.B2l = eW0l; j0.kA2 = 128;
                j0.bias = eb0;
                j0.ohi = h0h + (size_t)(t + 1) * BH;  j0.olo = h0l + (size_t)(t + 1) * BH;
            } else {
                int td = t - TENC;
                j0.A1h = h0h + (size_t)(TENC + td) * BH;  j0.A1l = h0l + (size_t)(TENC + td) * BH;
                j0.B1h = dU0h; j0.B1l = dU0l;
                j0.bias = db0; j0.dec = decin + td; j0.dW0 = dW0;
                j0.ohi = h0h + (size_t)(TENC + 1 + td) * BH;  j0.olo = h0l + (size_t)(TENC + 1 + td) * BH;
            }
        }
        if (w >= 1) {                        // layer-1 step w-1
            int t = w - 1;
            j1.active = 1;
            j1.kA1 = 512; j1.kA2 = 512;
            j1.c_state = c1;
            if (t < TENC) {
                j1.A1h = h1h + (size_t)t * BH;  j1.A1l = h1l + (size_t)t * BH;
                j1.B1h = eU1h; j1.B1l = eU1l;
                j1.A2h = h0h + (size_t)(t + 1) * BH;  j1.A2l = h0l + (size_t)(t + 1) * BH;
                j1.B2h = eW1h; j1.B2l = eW1l;
                j1.bias = eb1;
                j1.ohi = h1h + (size_t)(t + 1) * BH;  j1.olo = h1l + (size_t)(t + 1) * BH;
            } else {
                int td = t - TENC;
                j1.A1h = h1h + (size_t)(TENC + td) * BH;  j1.A1l = h1l + (size_t)(TENC + td) * BH;
                j1.B1h = dU1h; j1.B1l = dU1l;
                j1.A2h = h0h + (size_t)(TENC + 1 + td) * BH;  j1.A2l = h0l + (size_t)(TENC + 1 + td) * BH;
                j1.B2h = dW1h; j1.B2l = dW1l;
                j1.bias = db1;
                j1.ohi = h1h + (size_t)(TENC + 1 + td) * BH;  j1.olo = h1l + (size_t)(TENC + 1 + td) * BH;
            }
        }
        wave_step<<<g, 128, SMEM_BYTES>>>(j0, j1);
    }

    dense_kernel<<<(Bsz * SEG * 32) / 256, 256>>>(h1h, h1l, denseW, denseb, out);
}

// round 12
// speedup vs baseline: 1.8222x; 1.8222x over previous
#include <cuda_runtime.h>
#include <cuda_bf16.h>
#include <math.h>
#include <stdint.h>

#define Bsz   1024
#define TENC  64
#define SEG   32
#define Hdim  512
#define FOURH 2048
#define BH    (Bsz * Hdim)

#if defined(__CUDA_ARCH__) && (defined(__CUDA_ARCH_FEAT_SM103_ALL) || \
    defined(__CUDA_ARCH_FEAT_SM100_ALL) || defined(__CUDA_ARCH_SPECIFIC__) || \
    defined(__CUDA_ARCH_FAMILY_SPECIFIC__))
#define TC_OK 1
#else
#define TC_OK 0
#endif

// ------------------------- static scratch -------------------------
__device__ __nv_bfloat16 g_h0hi[(size_t)97 * BH];
__device__ __nv_bfloat16 g_h0lo[(size_t)97 * BH];
__device__ __nv_bfloat16 g_h1hi[(size_t)97 * BH];
__device__ __nv_bfloat16 g_h1lo[(size_t)97 * BH];
__device__ __nv_bfloat16 g_xhi[(size_t)65536 * 128];
__device__ __nv_bfloat16 g_xlo[(size_t)65536 * 128];
__device__ __nv_bfloat16 g_eU0h[(size_t)2048 * 512], g_eU0l[(size_t)2048 * 512];
__device__ __nv_bfloat16 g_eU1h[(size_t)2048 * 512], g_eU1l[(size_t)2048 * 512];
__device__ __nv_bfloat16 g_dU0h[(size_t)2048 * 512], g_dU0l[(size_t)2048 * 512];
__device__ __nv_bfloat16 g_dU1h[(size_t)2048 * 512], g_dU1l[(size_t)2048 * 512];
__device__ __nv_bfloat16 g_eW1h[(size_t)2048 * 512], g_eW1l[(size_t)2048 * 512];
__device__ __nv_bfloat16 g_dW1h[(size_t)2048 * 512], g_dW1l[(size_t)2048 * 512];
__device__ __nv_bfloat16 g_eW0h[(size_t)2048 * 128], g_eW0l[(size_t)2048 * 128];
__device__ unsigned int g_bar;

struct Params {
    __nv_bfloat16 *h0h, *h0l, *h1h, *h1l;
    const __nv_bfloat16 *xh, *xl;
    const __nv_bfloat16 *eU0h, *eU0l, *eU1h, *eU1l;
    const __nv_bfloat16 *dU0h, *dU0l, *dU1h, *dU1l;
    const __nv_bfloat16 *eW1h, *eW1l, *dW1h, *dW1l, *eW0h, *eW0l;
    const float *eb0, *eb1, *db0, *db1, *dW0, *dec;
};

// ------------------------- helpers -------------------------
__device__ __forceinline__ uint32_t smem_to_u32(const void* p) {
    uint32_t a;
    asm("{ .reg .u64 t; cvta.to.shared.u64 t, %1; cvt.u32.u64 %0, t; }" : "=r"(a) : "l"(p));
    return a;
}
__device__ __forceinline__ void lstm_gates(float zi, float zf, float zg, float zo,
                                           float cold, float& cn, float& h) {
    float ig = 1.f / (1.f + expf(-zi));
    float fg = 1.f / (1.f + expf(-zf));
    float gg = tanhf(zg);
    float og = 1.f / (1.f + expf(-zo));
    cn = fg * cold + ig * gg;
    h  = og * tanhf(cn);
}

#if TC_OK
__device__ __forceinline__ uint32_t elect_one_pred() {
    uint32_t pred;
    asm volatile("{\n\t.reg .pred p;\n\telect.sync _|p, 0xFFFFFFFF;\n\t"
                 "selp.b32 %0, 1, 0, p;\n\t}" : "=r"(pred));
    return pred;
}
#define TCGEN05_ALLOC(addr, n) \
    asm volatile("tcgen05.alloc.cta_group::1.sync.aligned.shared::cta.b32 [%0], %1;" \
                 :: "r"((uint32_t)(addr)), "r"((uint32_t)(n)) : "memory")
#define TCGEN05_DEALLOC(tm, n) \
    asm volatile("tcgen05.dealloc.cta_group::1.sync.aligned.b32 %0, %1;" :: "r"(tm), "r"((uint32_t)(n)))
#define TCGEN05_RELINQ() \
    asm volatile("tcgen05.relinquish_alloc_permit.cta_group::1.sync.aligned;")
#define TCGEN05_COMMIT(mb) \
    asm volatile("tcgen05.commit.cta_group::1.mbarrier::arrive::one.shared::cluster.b64 [%0];" \
                 :: "r"((uint32_t)(mb)) : "memory")
#define TCGEN05_WAIT_LD() asm volatile("tcgen05.wait::ld.sync.aligned;" ::: "memory")
#define TCGEN05_FENCE_AFTER() asm volatile("tcgen05.fence::after_thread_sync;" ::: "memory")
#define MBARRIER_INIT(mb, cnt) \
    asm volatile("mbarrier.init.shared.b64 [%0], %1;" :: "r"((uint32_t)(mb)), "r"((uint32_t)(cnt)) : "memory")
#define FENCE_PROXY_ASYNC() asm volatile("fence.proxy.async.shared::cta;" ::: "memory")
#define CP_ASYNC16(dst, src) \
    asm volatile("cp.async.cg.shared.global [%0], [%1], 16;" :: "r"((uint32_t)(dst)), "l"(src) : "memory")
#define CP_COMMIT() asm volatile("cp.async.commit_group;" ::: "memory")
#define CP_WAIT(n)  asm volatile("cp.async.wait_group %0;" :: "n"(n) : "memory")

#define MBARRIER_WAIT_PARITY(mb, par) do { \
    uint32_t _m = (uint32_t)(mb), _p = (uint32_t)(par), _d; \
    asm volatile("{\n\t.reg .pred p;\n\t" \
        "mbarrier.try_wait.parity.acquire.cta.shared::cta.b64 p, [%1], %2;\n\t" \
        "selp.b32 %0, 1, 0, p;\n\t}" : "=r"(_d) : "r"(_m), "r"(_p) : "memory"); \
    if (!_d) { \
        asm volatile("{\n\t.reg .pred P1;\n\t" \
            "WL_%=:\n\t" \
            "mbarrier.try_wait.parity.acquire.cta.shared::cta.b64 P1, [%0], %1, 0x989680;\n\t" \
            "@P1 bra.uni WD_%=;\n\tbra.uni WL_%=;\n\tWD_%=:\n\t}" \
            :: "r"(_m), "r"(_p) : "memory"); \
    } \
} while (0)

#define TCGEN05_LD_32X32B_X32(r, ta) \
    asm volatile("tcgen05.ld.sync.aligned.32x32b.x32.b32 " \
        "{%0, %1, %2, %3, %4, %5, %6, %7, %8, %9, %10, %11, %12, %13, %14, %15, " \
        " %16, %17, %18, %19, %20, %21, %22, %23, %24, %25, %26, %27, %28, %29, %30, %31}, [%32];" \
        : "=r"((r)[0]), "=r"((r)[1]), "=r"((r)[2]), "=r"((r)[3]), "=r"((r)[4]), "=r"((r)[5]), \
          "=r"((r)[6]), "=r"((r)[7]), "=r"((r)[8]), "=r"((r)[9]), "=r"((r)[10]), "=r"((r)[11]), \
          "=r"((r)[12]), "=r"((r)[13]), "=r"((r)[14]), "=r"((r)[15]), "=r"((r)[16]), "=r"((r)[17]), \
          "=r"((r)[18]), "=r"((r)[19]), "=r"((r)[20]), "=r"((r)[21]), "=r"((r)[22]), "=r"((r)[23]), \
          "=r"((r)[24]), "=r"((r)[25]), "=r"((r)[26]), "=r"((r)[27]), "=r"((r)[28]), "=r"((r)[29]), \
          "=r"((r)[30]), "=r"((r)[31]) : "r"(ta))

static constexpr uint64_t SMEM_DESC_BASE_SW128 =
    (uint64_t(2) << 61) | (uint64_t(1) << 46) | (uint64_t(64) << 32) | (uint64_t(1) << 16);
#define MAKE_SMEM_DESC(a) (SMEM_DESC_BASE_SW128 | ((uint64_t)((a) >> 4) & 0x3FFF))
#define MMA_IDESC 0x8200490u   // F32 acc, bf16 x bf16, M=128, N=128

__device__ __forceinline__ void mma_f16_ss(uint32_t d, uint64_t a, uint64_t b, bool acc) {
    uint32_t en = acc ? 1u : 0u;
    asm volatile("{\n\t.reg .pred p;\n\tsetp.ne.u32 p, %5, 0;\n\t"
        "tcgen05.mma.cta_group::1.kind::f16 [%0], %1, %2, %3, {%4, %4, %4, %4}, p;\n\t}"
        :: "r"(d), "l"(a), "l"(b), "r"(MMA_IDESC), "r"(0u), "r"(en) : "memory");
}
#endif // TC_OK

// ------------------- fused conversion (1 launch) -------------------
#define WK (2048 * 512)
__global__ void __launch_bounds__(256) conv_all(
    const float* __restrict__ eU0, const float* __restrict__ eU1,
    const float* __restrict__ dU0, const float* __restrict__ dU1,
    const float* __restrict__ eW1, const float* __restrict__ dW1,
    const float* __restrict__ eW0, const float* __restrict__ x,
    __nv_bfloat16* eU0h, __nv_bfloat16* eU0l, __nv_bfloat16* eU1h, __nv_bfloat16* eU1l,
    __nv_bfloat16* dU0h, __nv_bfloat16* dU0l, __nv_bfloat16* dU1h, __nv_bfloat16* dU1l,
    __nv_bfloat16* eW1h, __nv_bfloat16* eW1l, __nv_bfloat16* dW1h, __nv_bfloat16* dW1l,
    __nv_bfloat16* eW0h, __nv_bfloat16* eW0l, __nv_bfloat16* xh, __nv_bfloat16* xl)
{
    size_t idx = (size_t)blockIdx.x * 256 + threadIdx.x;
    const size_t seg6 = (size_t)6 * WK;
    const size_t seg7 = seg6 + 2048 * 128;
    const size_t segE = seg7 + (size_t)65536 * 128;
    if (idx >= segE) return;
    if (idx < seg6) {
        int which = (int)(idx / WK), wk = (int)(idx % WK);
        int n = wk / 512, k = wk % 512;
        int r = n & 127, hT = n >> 7;
        int orig = (r & 3) * 512 + hT * 32 + (r >> 2);
        const float* s = (which == 0) ? eU0 : (which == 1) ? eU1 : (which == 2) ? dU0
                        : (which == 3) ? dU1 : (which == 4) ? eW1 : dW1;
        __nv_bfloat16* dh = (which == 0) ? eU0h : (which == 1) ? eU1h : (which == 2) ? dU0h
                           : (which == 3) ? dU1h : (which == 4) ? eW1h : dW1h;
        __nv_bfloat16* dl = (which == 0) ? eU0l : (which == 1) ? eU1l : (which == 2) ? dU0l
                           : (which == 3) ? dU1l : (which == 4) ? eW1l : dW1l;
        float v = s[(size_t)k * FOURH + orig];
        __nv_bfloat16 h = __float2bfloat16(v);
        dh[wk] = h; dl[wk] = __float2bfloat16(v - __bfloat162float(h));
    } else if (idx < seg7) {
        int wk = (int)(idx - seg6);
        int n = wk / 128, k = wk % 128;
        int r = n & 127, hT = n >> 7;
        int orig = (r & 3) * 512 + hT * 32 + (r >> 2);
        float v = (k < 121) ? eW0[(size_t)k * FOURH + orig] : 0.f;
        __nv_bfloat16 h = __float2bfloat16(v);
        eW0h[wk] = h; eW0l[wk] = __float2bfloat16(v - __bfloat162float(h));
    } else {
        size_t wk = idx - seg7;
        int m = (int)(wk >> 7), k = (int)(wk & 127);
        int t = m >> 10, b = m & 1023;
        float v = (k < 121) ? x[(size_t)b * (TENC * 121) + t * 121 + k] : 0.f;
        __nv_bfloat16 h = __float2bfloat16(v);
        xh[wk] = h; xl[wk] = __float2bfloat16(v - __bfloat162float(h));
    }
}

__global__ void __launch_bounds__(256) zero_init(
    __nv_bfloat16* h0h, __nv_bfloat16* h0l, __nv_bfloat16* h1h, __nv_bfloat16* h1l)
{
    int i = blockIdx.x * 256 + threadIdx.x;
    if (i == 0) g_bar = 0;                 // reset persistent-kernel barrier each replay
    if (i >= BH) return;
    __nv_bfloat16 z = __float2bfloat16(0.f);
    h0h[i] = z; h0l[i] = z; h1h[i] = z; h1l[i] = z;
}

// ------------------- persistent wavefront kernel -------------------
// grid (8, 8, 2) = 128 CTAs, 1/SM (smem-bound), all co-resident. 128 threads.
#define STAGE_BYTES 98304
#define SMEM_C_OFF  (1024 + 2 * STAGE_BYTES)             // 197632
#define SMEM_BYTES  (SMEM_C_OFF + 128 * 65 * 4)           // 230912

__global__ void __launch_bounds__(128) lstm_persist(Params P)
{
    extern __shared__ char smem[];
    const uint32_t sb = smem_to_u32(smem);
    const uint32_t tb = (sb + 1023u) & ~1023u;
    char* smemc = smem + (tb - sb);

    const int tid = threadIdx.x;
    const int nb = blockIdx.x;                 // col tile 0..7 (256 perm cols)
    const int z  = (int)blockIdx.z;            // 0 = layer0, 1 = layer1
    const size_t rowBase = (size_t)blockIdx.y * 128;
    const size_t colBase = (size_t)nb * 256;

    float* scf = (float*)(smemc + SMEM_C_OFF); // [128][65] persistent c tile
    for (int i = tid; i < 128 * 65; i += 128) scf[i] = 0.f;

#if TC_OK
    if (tid < 32) { TCGEN05_ALLOC(tb, 256); TCGEN05_RELINQ(); }
    if (tid == 0) {
        MBARRIER_INIT(tb + 24, 1);   // done buf0
        MBARRIER_INIT(tb + 32, 1);   // done buf1
        MBARRIER_INIT(tb + 40, 1);   // MBF
    }
    __syncthreads();
    uint32_t tmem;
    asm volatile("ld.shared.b32 %0, [%1];" : "=r"(tmem) : "r"(tb));
    int cnt0 = 0, cnt1 = 0, mbfc = 0;
#else
    __syncthreads();
#endif

    for (int w = 0; w <= 96; w++) {
        const bool active = (z == 0) ? (w < 96) : (w >= 1);
        if (active) {
            const int t = (z == 0) ? w : (w - 1);
            const __nv_bfloat16 *A1h, *A1l, *B1h, *B1l;
            const __nv_bfloat16 *A2h = nullptr, *A2l = nullptr, *B2h = nullptr, *B2l = nullptr;
            const float *bias, *dec = nullptr, *dW0p = nullptr;
            __nv_bfloat16 *ohi, *olo;
            int kA2 = 0;
            if (z == 0) {
                A1h = P.h0h + (size_t)t * BH;  A1l = P.h0l + (size_t)t * BH;
                ohi = P.h0h + (size_t)(t + 1) * BH;  olo = P.h0l + (size_t)(t + 1) * BH;
                if (t < TENC) {
                    B1h = P.eU0h; B1l = P.eU0l;
                    A2h = P.xh + (size_t)t * 1024 * 128;  A2l = P.xl + (size_t)t * 1024 * 128;
                    B2h = P.eW0h; B2l = P.eW0l; kA2 = 128;
                    bias = P.eb0;
                } else {
                    B1h = P.dU0h; B1l = P.dU0l;
                    bias = P.db0; dec = P.dec + (t - TENC); dW0p = P.dW0;
                }
            } else {
                A1h = P.h1h + (size_t)t * BH;  A1l = P.h1l + (size_t)t * BH;
                ohi = P.h1h + (size_t)(t + 1) * BH;  olo = P.h1l + (size_t)(t + 1) * BH;
                A2h = P.h0h + (size_t)(t + 1) * BH;  A2l = P.h0l + (size_t)(t + 1) * BH;
                kA2 = 512;
                if (t < TENC) { B1h = P.eU1h; B1l = P.eU1l; B2h = P.eW1h; B2l = P.eW1l; bias = P.eb1; }
                else          { B1h = P.dU1h; B1l = P.dU1l; B2h = P.dW1h; B2l = P.dW1l; bias = P.db1; }
            }
            const int kA1 = 512;
            const int ch1 = 8;
            const int nch = ch1 + (kA2 >> 6);

#if TC_OK
#define LOAD_CHUNK(cc) do { \
        const uint32_t _st = tb + 1024 + (uint32_t)((cc) & 1) * STAGE_BYTES; \
        const __nv_bfloat16 *_Ah, *_Al, *_Bh, *_Bl; int _kA, _ko; \
        if ((cc) < ch1) { _Ah = A1h; _Al = A1l; _Bh = B1h; _Bl = B1l; _kA = kA1; _ko = (cc) * 64; } \
        else { _Ah = A2h; _Al = A2l; _Bh = B2h; _Bl = B2l; _kA = kA2; _ko = ((cc) - ch1) * 64; } \
        _Pragma("unroll") \
        for (int _i = 0; _i < 8; _i++) { \
            int _a = _i * 128 + tid; \
            int _r = _a >> 3, _s = _a & 7; \
            uint32_t _off = (uint32_t)(_r * 128 + _s * 16); \
            _off ^= (_off >> 3) & 0x70; \
            size_t _ga = (rowBase + _r) * (size_t)_kA + _ko + _s * 8; \
            CP_ASYNC16(_st + _off, _Ah + _ga); \
            CP_ASYNC16(_st + 16384 + _off, _Al + _ga); \
        } \
        _Pragma("unroll") \
        for (int _i = 0; _i < 16; _i++) { \
            int _a = _i * 128 + tid; \
            int _r = _a >> 3, _s = _a & 7; \
            uint32_t _off = (uint32_t)(_r * 128 + _s * 16); \
            _off ^= (_off >> 3) & 0x70; \
            size_t _gb = (colBase + _r) * (size_t)_kA + _ko + _s * 8; \
            CP_ASYNC16(_st + 32768 + _off, _Bh + _gb); \
            CP_ASYNC16(_st + 65536 + _off, _Bl + _gb); \
        } \
        CP_COMMIT(); \
    } while (0)

            LOAD_CHUNK(0);
            LOAD_CHUNK(1);

            for (int c = 0; c < nch; c++) {
                if (c == nch - 1) CP_WAIT(0); else CP_WAIT(1);
                __syncthreads();
                if (tid < 32 && elect_one_pred()) {
                    const uint32_t st = tb + 1024 + (uint32_t)(c & 1) * STAGE_BYTES;
                    uint64_t adh = MAKE_SMEM_DESC(st);
                    uint64_t adl = MAKE_SMEM_DESC(st + 16384);
                    uint64_t bdh = MAKE_SMEM_DESC(st + 32768);
                    uint64_t bdl = MAKE_SMEM_DESC(st + 65536);
#pragma unroll
                    for (int term = 0; term < 3; term++) {
                        uint64_t ad = (term == 1) ? adl : adh;
                        uint64_t bd = (term == 2) ? bdl : bdh;
#pragma unroll
                        for (int j = 0; j < 4; j++) {
                            bool acc = !(c == 0 && term == 0 && j == 0);
                            mma_f16_ss(tmem,       ad + j * 2, bd + j * 2,        acc);
                            mma_f16_ss(tmem + 128, ad + j * 2, bd + 1024 + j * 2, acc);
                        }
                    }
                    TCGEN05_COMMIT(tb + 24 + (uint32_t)(c & 1) * 8);
                }
                int cn = (c & 1) ? cnt1 : cnt0;
                if (c + 2 < nch) {
                    MBARRIER_WAIT_PARITY(tb + 24 + (uint32_t)(c & 1) * 8, cn & 1);
                    LOAD_CHUNK(c + 2);
                }
                if (c & 1) cnt1++; else cnt0++;
            }
#undef LOAD_CHUNK

            if (tid < 32 && elect_one_pred()) TCGEN05_COMMIT(tb + 40);
            __syncthreads();
            MBARRIER_WAIT_PARITY(tb + 40, mbfc & 1);
            mbfc++;
            TCGEN05_FENCE_AFTER();

            // ---- epilogue: c stays in SMEM; h staged then coalesced writeback ----
            __nv_bfloat16* shi = (__nv_bfloat16*)(smemc + 1024);           // [128][66]
            __nv_bfloat16* slo = (__nv_bfloat16*)(smemc + 1024 + 16896);   // [128][66]
            const size_t row = rowBase + tid;
            const float dv = dec ? dec[row * SEG] : 0.f;

            for (int q = 0; q < 8; q++) {
                uint32_t dr[32];
                TCGEN05_LD_32X32B_X32(dr, tmem + q * 32);
                TCGEN05_WAIT_LD();
                const int nlb = ((q & 4) ? 32 : 0) + (q & 3) * 8;
#pragma unroll
                for (int jj = 0; jj < 8; jj++) {
                    int nl = nlb + jj;
                    int hg = nb * 64 + nl;
                    float zi = __uint_as_float(dr[jj * 4 + 0]) + bias[hg];
                    float zf = __uint_as_float(dr[jj * 4 + 1]) + bias[512 + hg];
                    float zg = __uint_as_float(dr[jj * 4 + 2]) + bias[1024 + hg];
                    float zo = __uint_as_float(dr[jj * 4 + 3]) + bias[1536 + hg];
                    if (dec) {
                        zi += dv * dW0p[hg];
                        zf += dv * dW0p[512 + hg];
                        zg += dv * dW0p[1024 + hg];
                        zo += dv * dW0p[1536 + hg];
                    }
                    float cn2, h;
                    lstm_gates(zi, zf, zg, zo, scf[tid * 65 + nl], cn2, h);
                    scf[tid * 65 + nl] = cn2;
                    __nv_bfloat16 hh = __float2bfloat16(h);
                    shi[tid * 66 + nl] = hh;
                    slo[tid * 66 + nl] = __float2bfloat16(h - __bfloat162float(hh));
                }
            }
            __syncthreads();
#pragma unroll 4
            for (int i = 0; i < 64; i++) {
                int idx = i * 128 + tid, r = idx >> 6, cc = idx & 63;
                size_t o = (rowBase + r) * Hdim + nb * 64 + cc;
                ohi[o] = shi[r * 66 + cc];
                olo[o] = slo[r * 66 + cc];
            }
#else
            // ---------- FFMA fallback (non-'a' pass; unused when 'a' cubin loads) ----------
            float* sA = (float*)(smemc + 1024);                // [32][132]
            float* sB = (float*)(smemc + 1024 + 16896);        // [32][68]
            const int tr = tid >> 3, tc8 = tid & 7;
            for (int pass = 0; pass < 4; pass++) {
                float acc[8][8];
#pragma unroll
                for (int r = 0; r < 8; r++)
#pragma unroll
                    for (int j = 0; j < 8; j++) acc[r][j] = 0.f;
                for (int part = 0; part < 2; part++) {
                    if (part == 1 && !A2h) break;
                    const __nv_bfloat16* Ah = part ? A2h : A1h;
                    const __nv_bfloat16* Al = part ? A2l : A1l;
                    const __nv_bfloat16* Bh = part ? B2h : B1h;
                    const __nv_bfloat16* Bl = part ? B2l : B1l;
                    const int kA = part ? kA2 : kA1;
                    for (int k0 = 0; k0 < kA; k0 += 32) {
                        __syncthreads();
#pragma unroll 4
                        for (int i = 0; i < 32; i++) {
                            int idx = i * 128 + tid, r = idx >> 5, kk = idx & 31;
                            size_t ao = (rowBase + r) * (size_t)kA + k0 + kk;
                            sA[kk * 132 + r] = __bfloat162float(Ah[ao]) + __bfloat162float(Al[ao]);
                        }
#pragma unroll 2
                        for (int i = 0; i < 16; i++) {
                            int idx = i * 128 + tid, r = idx >> 5, kk = idx & 31;
                            size_t bo = (colBase + pass * 64 + r) * (size_t)kA + k0 + kk;
                            sB[kk * 68 + r] = __bfloat162float(Bh[bo]) + __bfloat162float(Bl[bo]);
                        }
                        __syncthreads();
#pragma unroll
                        for (int k = 0; k < 32; k++) {
                            float a[8], b[8];
#pragma unroll
                            for (int r = 0; r < 8; r++) a[r] = sA[k * 132 + tr * 8 + r];
#pragma unroll
                            for (int j = 0; j < 8; j++) b[j] = sB[k * 68 + tc8 * 8 + j];
#pragma unroll
                            for (int r = 0; r < 8; r++)
#pragma unroll
                                for (int j = 0; j < 8; j++) acc[r][j] += a[r] * b[j];
                        }
                    }
                }
                __syncthreads();
#pragma unroll
                for (int r = 0; r < 8; r++) {
                    int lr = tr * 8 + r;
                    size_t row = rowBase + lr;
                    float dvr = dec ? dec[row * SEG] : 0.f;
#pragma unroll
                    for (int q = 0; q < 2; q++) {
                        int nl = ((pass & 2) ? 32 : 0) + (pass & 1) * 16 + tc8 * 2 + q;
                        int hg = nb * 64 + nl;
                        float zi = acc[r][q * 4 + 0] + bias[hg];
                        float zf = acc[r][q * 4 + 1] + bias[512 + hg];
                        float zg = acc[r][q * 4 + 2] + bias[1024 + hg];
                        float zo = acc[r][q * 4 + 3] + bias[1536 + hg];
                        if (dec) {
                            zi += dvr * dW0p[hg];
                            zf += dvr * dW0p[512 + hg];
                            zg += dvr * dW0p[1024 + hg];
                            zo += dvr * dW0p[1536 + hg];
                        }
                        size_t o = row * Hdim + hg;
                        float cn2, h;
                        lstm_gates(zi, zf, zg, zo, scf[lr * 65 + nl], cn2, h);
                        scf[lr * 65 + nl] = cn2;
                        __nv_bfloat16 hh = __float2bfloat16(h);
                        ohi[o] = hh;
                        olo[o] = __float2bfloat16(h - __bfloat162float(hh));
                    }
                }
                __syncthreads();
            }
#endif
        }

        // -------- grid-wide wave barrier (all 128 CTAs co-resident) --------
        __threadfence();
        __syncthreads();
        if (tid == 0) {
            atomicAdd(&g_bar, 1u);
            unsigned tgt = 128u * (unsigned)(w + 1), v;
            do {
                asm volatile("ld.acquire.gpu.u32 %0, [%1];" : "=r"(v) : "l"(&g_bar) : "memory");
            } while (v < tgt);
        }
        __syncthreads();
    }

#if TC_OK
    if (tid < 32) TCGEN05_DEALLOC(tmem, 256);
#endif
}

// ------------------- final dense -------------------
__global__ void __launch_bounds__(256) dense_kernel(
    const __nv_bfloat16* __restrict__ hi, const __nv_bfloat16* __restrict__ lo,
    const float* __restrict__ W, const float* __restrict__ bb, float* __restrict__ out)
{
    int wid = (blockIdx.x * blockDim.x + threadIdx.x) >> 5;
    int lane = threadIdx.x & 31;
    if (wid >= Bsz * SEG) return;
    int b = wid / SEG, s = wid % SEG;
    size_t base = (size_t)(TENC + 1 + s) * BH + (size_t)b * Hdim;
    float sum = 0.f;
#pragma unroll 4
    for (int k = lane; k < Hdim; k += 32)
        sum += (__bfloat162float(hi[base + k]) + __bfloat162float(lo[base + k])) * W[k];
#pragma unroll
    for (int o = 16; o > 0; o >>= 1) sum += __shfl_down_sync(0xffffffffu, sum, o);
    if (lane == 0) out[(size_t)b * SEG + s] = sum + bb[0];
}

// ------------------- host -------------------
extern "C" void kernel_launch(void* const* d_in, const int* in_sizes, int n_in,
                              void* d_out, int out_size)
{
    const float* x      = (const float*)d_in[0];
    const float* decin  = (const float*)d_in[1];
    const float* eW0    = (const float*)d_in[2];
    const float* eU0    = (const float*)d_in[3];
    const float* eb0    = (const float*)d_in[4];
    const float* eW1    = (const float*)d_in[5];
    const float* eU1    = (const float*)d_in[6];
    const float* eb1    = (const float*)d_in[7];
    const float* dW0    = (const float*)d_in[8];
    const float* dU0    = (const float*)d_in[9];
    const float* db0    = (const float*)d_in[10];
    const float* dW1    = (const float*)d_in[11];
    const float* dU1    = (const float*)d_in[12];
    const float* db1    = (const float*)d_in[13];
    const float* denseW = (const float*)d_in[14];
    const float* denseb = (const float*)d_in[15];
    float* out = (float*)d_out;

    cudaFuncSetAttribute(lstm_persist, cudaFuncAttributeMaxDynamicSharedMemorySize, SMEM_BYTES);

    Params P;
    cudaGetSymbolAddress((void**)&P.h0h, g_h0hi);
    cudaGetSymbolAddress((void**)&P.h0l, g_h0lo);
    cudaGetSymbolAddress((void**)&P.h1h, g_h1hi);
    cudaGetSymbolAddress((void**)&P.h1l, g_h1lo);
    cudaGetSymbolAddress((void**)&P.xh, g_xhi);
    cudaGetSymbolAddress((void**)&P.xl, g_xlo);
    cudaGetSymbolAddress((void**)&P.eU0h, g_eU0h); cudaGetSymbolAddress((void**)&P.eU0l, g_eU0l);
    cudaGetSymbolAddress((void**)&P.eU1h, g_eU1h); cudaGetSymbolAddress((void**)&P.eU1l, g_eU1l);
    cudaGetSymbolAddress((void**)&P.dU0h, g_dU0h); cudaGetSymbolAddress((void**)&P.dU0l, g_dU0l);
    cudaGetSymbolAddress((void**)&P.dU1h, g_dU1h); cudaGetSymbolAddress((void**)&P.dU1l, g_dU1l);
    cudaGetSymbolAddress((void**)&P.eW1h, g_eW1h); cudaGetSymbolAddress((void**)&P.eW1l, g_eW1l);
    cudaGetSymbolAddress((void**)&P.dW1h, g_dW1h); cudaGetSymbolAddress((void**)&P.dW1l, g_dW1l);
    cudaGetSymbolAddress((void**)&P.eW0h, g_eW0h); cudaGetSymbolAddress((void**)&P.eW0l, g_eW0l);
    P.eb0 = eb0; P.eb1 = eb1; P.db0 = db0; P.db1 = db1; P.dW0 = dW0; P.dec = decin;

    {
        size_t total = (size_t)6 * WK + 2048 * 128 + (size_t)65536 * 128;
        conv_all<<<(int)((total + 255) / 256), 256>>>(
            eU0, eU1, dU0, dU1, eW1, dW1, eW0, x,
            (__nv_bfloat16*)P.eU0h, (__nv_bfloat16*)P.eU0l,
            (__nv_bfloat16*)P.eU1h, (__nv_bfloat16*)P.eU1l,
            (__nv_bfloat16*)P.dU0h, (__nv_bfloat16*)P.dU0l,
            (__nv_bfloat16*)P.dU1h, (__nv_bfloat16*)P.dU1l,
            (__nv_bfloat16*)P.eW1h, (__nv_bfloat16*)P.eW1l,
            (__nv_bfloat16*)P.dW1h, (__nv_bfloat16*)P.dW1l,
            (__nv_bfloat16*)P.eW0h, (__nv_bfloat16*)P.eW0l,
            (__nv_bfloat16*)P.xh, (__nv_bfloat16*)P.xl);
    }
    zero_init<<<(BH + 255) / 256, 256>>>(P.h0h, P.h0l, P.h1h, P.h1l);

    lstm_persist<<<dim3(8, 8, 2), 128, SMEM_BYTES>>>(P);

    dense_kernel<<<(Bsz * SEG * 32) / 256, 256>>>(P.h1h, P.h1l, denseW, denseb, out);
}

// round 13
// speedup vs baseline: 2.5451x; 1.3967x over previous
#include <cuda_runtime.h>
#include <cuda_fp16.h>
#include <math.h>
#include <stdint.h>

#define Bsz   1024
#define TENC  64
#define SEG   32
#define Hdim  512
#define FOURH 2048
#define BH    (Bsz * Hdim)

#if defined(__CUDA_ARCH__) && (defined(__CUDA_ARCH_FEAT_SM103_ALL) || \
    defined(__CUDA_ARCH_FEAT_SM100_ALL) || defined(__CUDA_ARCH_SPECIFIC__) || \
    defined(__CUDA_ARCH_FAMILY_SPECIFIC__))
#define TC_OK 1
#else
#define TC_OK 0
#endif

// ------------------------- static scratch -------------------------
__device__ __half g_h0[(size_t)97 * BH];
__device__ __half g_h1[(size_t)97 * BH];
__device__ __half g_x[(size_t)65536 * 128];
__device__ __half g_eU0[(size_t)2048 * 512];
__device__ __half g_eU1[(size_t)2048 * 512];
__device__ __half g_dU0[(size_t)2048 * 512];
__device__ __half g_dU1[(size_t)2048 * 512];
__device__ __half g_eW1[(size_t)2048 * 512];
__device__ __half g_dW1[(size_t)2048 * 512];
__device__ __half g_eW0[(size_t)2048 * 128];
__device__ unsigned int g_bar;

struct Params {
    __half *h0, *h1;
    const __half *x;
    const __half *eU0, *eU1, *dU0, *dU1, *eW1, *dW1, *eW0;
    const float *eb0, *eb1, *db0, *db1, *dW0, *dec;
};

// ------------------------- helpers -------------------------
__device__ __forceinline__ uint32_t smem_to_u32(const void* p) {
    uint32_t a;
    asm("{ .reg .u64 t; cvta.to.shared.u64 t, %1; cvt.u32.u64 %0, t; }" : "=r"(a) : "l"(p));
    return a;
}
__device__ __forceinline__ void lstm_gates(float zi, float zf, float zg, float zo,
                                           float cold, float& cn, float& h) {
    float ig = 1.f / (1.f + expf(-zi));
    float fg = 1.f / (1.f + expf(-zf));
    float gg = tanhf(zg);
    float og = 1.f / (1.f + expf(-zo));
    cn = fg * cold + ig * gg;
    h  = og * tanhf(cn);
}

#if TC_OK
__device__ __forceinline__ uint32_t elect_one_pred() {
    uint32_t pred;
    asm volatile("{\n\t.reg .pred p;\n\telect.sync _|p, 0xFFFFFFFF;\n\t"
                 "selp.b32 %0, 1, 0, p;\n\t}" : "=r"(pred));
    return pred;
}
#define TCGEN05_ALLOC(addr, n) \
    asm volatile("tcgen05.alloc.cta_group::1.sync.aligned.shared::cta.b32 [%0], %1;" \
                 :: "r"((uint32_t)(addr)), "r"((uint32_t)(n)) : "memory")
#define TCGEN05_DEALLOC(tm, n) \
    asm volatile("tcgen05.dealloc.cta_group::1.sync.aligned.b32 %0, %1;" :: "r"(tm), "r"((uint32_t)(n)))
#define TCGEN05_RELINQ() \
    asm volatile("tcgen05.relinquish_alloc_permit.cta_group::1.sync.aligned;")
#define TCGEN05_COMMIT(mb) \
    asm volatile("tcgen05.commit.cta_group::1.mbarrier::arrive::one.shared::cluster.b64 [%0];" \
                 :: "r"((uint32_t)(mb)) : "memory")
#define TCGEN05_WAIT_LD() asm volatile("tcgen05.wait::ld.sync.aligned;" ::: "memory")
#define TCGEN05_FENCE_AFTER() asm volatile("tcgen05.fence::after_thread_sync;" ::: "memory")
#define MBARRIER_INIT(mb, cnt) \
    asm volatile("mbarrier.init.shared.b64 [%0], %1;" :: "r"((uint32_t)(mb)), "r"((uint32_t)(cnt)) : "memory")
#define FENCE_PROXY_ASYNC() asm volatile("fence.proxy.async.shared::cta;" ::: "memory")
#define CP_ASYNC16(dst, src) \
    asm volatile("cp.async.cg.shared.global [%0], [%1], 16;" :: "r"((uint32_t)(dst)), "l"(src) : "memory")
#define CP_COMMIT() asm volatile("cp.async.commit_group;" ::: "memory")
#define CP_WAIT(n)  asm volatile("cp.async.wait_group %0;" :: "n"(n) : "memory")

#define MBARRIER_WAIT_PARITY(mb, par) do { \
    uint32_t _m = (uint32_t)(mb), _p = (uint32_t)(par), _d; \
    asm volatile("{\n\t.reg .pred p;\n\t" \
        "mbarrier.try_wait.parity.acquire.cta.shared::cta.b64 p, [%1], %2;\n\t" \
        "selp.b32 %0, 1, 0, p;\n\t}" : "=r"(_d) : "r"(_m), "r"(_p) : "memory"); \
    if (!_d) { \
        asm volatile("{\n\t.reg .pred P1;\n\t" \
            "WL_%=:\n\t" \
            "mbarrier.try_wait.parity.acquire.cta.shared::cta.b64 P1, [%0], %1, 0x989680;\n\t" \
            "@P1 bra.uni WD_%=;\n\tbra.uni WL_%=;\n\tWD_%=:\n\t}" \
            :: "r"(_m), "r"(_p) : "memory"); \
    } \
} while (0)

#define TCGEN05_LD_32X32B_X32(r, ta) \
    asm volatile("tcgen05.ld.sync.aligned.32x32b.x32.b32 " \
        "{%0, %1, %2, %3, %4, %5, %6, %7, %8, %9, %10, %11, %12, %13, %14, %15, " \
        " %16, %17, %18, %19, %20, %21, %22, %23, %24, %25, %26, %27, %28, %29, %30, %31}, [%32];" \
        : "=r"((r)[0]), "=r"((r)[1]), "=r"((r)[2]), "=r"((r)[3]), "=r"((r)[4]), "=r"((r)[5]), \
          "=r"((r)[6]), "=r"((r)[7]), "=r"((r)[8]), "=r"((r)[9]), "=r"((r)[10]), "=r"((r)[11]), \
          "=r"((r)[12]), "=r"((r)[13]), "=r"((r)[14]), "=r"((r)[15]), "=r"((r)[16]), "=r"((r)[17]), \
          "=r"((r)[18]), "=r"((r)[19]), "=r"((r)[20]), "=r"((r)[21]), "=r"((r)[22]), "=r"((r)[23]), \
          "=r"((r)[24]), "=r"((r)[25]), "=r"((r)[26]), "=r"((r)[27]), "=r"((r)[28]), "=r"((r)[29]), \
          "=r"((r)[30]), "=r"((r)[31]) : "r"(ta))

static constexpr uint64_t SMEM_DESC_BASE_SW128 =
    (uint64_t(2) << 61) | (uint64_t(1) << 46) | (uint64_t(64) << 32) | (uint64_t(1) << 16);
#define MAKE_SMEM_DESC(a) (SMEM_DESC_BASE_SW128 | ((uint64_t)((a) >> 4) & 0x3FFF))
// kind::f16, fp16 inputs (atype=btype=0), F32 acc, M=128, N=128
#define MMA_IDESC 0x8200010u

__device__ __forceinline__ void mma_f16_ss(uint32_t d, uint64_t a, uint64_t b, bool acc) {
    uint32_t en = acc ? 1u : 0u;
    asm volatile("{\n\t.reg .pred p;\n\tsetp.ne.u32 p, %5, 0;\n\t"
        "tcgen05.mma.cta_group::1.kind::f16 [%0], %1, %2, %3, {%4, %4, %4, %4}, p;\n\t}"
        :: "r"(d), "l"(a), "l"(b), "r"(MMA_IDESC), "r"(0u), "r"(en) : "memory");
}
#endif // TC_OK

// ------------------- fused conversion (1 launch) -------------------
#define WK (2048 * 512)
__global__ void __launch_bounds__(256) conv_all(
    const float* __restrict__ eU0, const float* __restrict__ eU1,
    const float* __restrict__ dU0, const float* __restrict__ dU1,
    const float* __restrict__ eW1, const float* __restrict__ dW1,
    const float* __restrict__ eW0, const float* __restrict__ x,
    __half* oeU0, __half* oeU1, __half* odU0, __half* odU1,
    __half* oeW1, __half* odW1, __half* oeW0, __half* ox)
{
    size_t idx = (size_t)blockIdx.x * 256 + threadIdx.x;
    const size_t seg6 = (size_t)6 * WK;
    const size_t seg7 = seg6 + 2048 * 128;
    const size_t segE = seg7 + (size_t)65536 * 128;
    if (idx >= segE) return;
    if (idx < seg6) {
        int which = (int)(idx / WK), wk = (int)(idx % WK);
        int n = wk / 512, k = wk % 512;
        int r = n & 127, hT = n >> 7;
        int orig = (r & 3) * 512 + hT * 32 + (r >> 2);
        const float* s = (which == 0) ? eU0 : (which == 1) ? eU1 : (which == 2) ? dU0
                        : (which == 3) ? dU1 : (which == 4) ? eW1 : dW1;
        __half* d = (which == 0) ? oeU0 : (which == 1) ? oeU1 : (which == 2) ? odU0
                   : (which == 3) ? odU1 : (which == 4) ? oeW1 : odW1;
        d[wk] = __float2half(s[(size_t)k * FOURH + orig]);
    } else if (idx < seg7) {
        int wk = (int)(idx - seg6);
        int n = wk / 128, k = wk % 128;
        int r = n & 127, hT = n >> 7;
        int orig = (r & 3) * 512 + hT * 32 + (r >> 2);
        oeW0[wk] = __float2half((k < 121) ? eW0[(size_t)k * FOURH + orig] : 0.f);
    } else {
        size_t wk = idx - seg7;
        int m = (int)(wk >> 7), k = (int)(wk & 127);
        int t = m >> 10, b = m & 1023;
        ox[wk] = __float2half((k < 121) ? x[(size_t)b * (TENC * 121) + t * 121 + k] : 0.f);
    }
}

__global__ void __launch_bounds__(256) zero_init(__half* h0, __half* h1)
{
    int i = blockIdx.x * 256 + threadIdx.x;
    if (i == 0) g_bar = 0;                 // reset persistent barrier each replay
    if (i >= BH) return;
    __half z = __float2half(0.f);
    h0[i] = z; h1[i] = z;
}

// ------------------- persistent wavefront kernel -------------------
// grid (8, 8, 2) = 128 CTAs, 1/SM, all co-resident. 128 threads.
#define STAGE_BYTES 49152
#define SMEM_C_OFF  (1024 + 2 * STAGE_BYTES)             // 99328
#define SMEM_BYTES  (SMEM_C_OFF + 128 * 65 * 4)           // 132608

__global__ void __launch_bounds__(128) lstm_persist(Params P)
{
    extern __shared__ char smem[];
    const uint32_t sb = smem_to_u32(smem);
    const uint32_t tb = (sb + 1023u) & ~1023u;
    char* smemc = smem + (tb - sb);

    const int tid = threadIdx.x;
    const int nb = blockIdx.x;                 // col tile 0..7 (256 perm cols)
    const int z  = (int)blockIdx.z;            // 0 = layer0, 1 = layer1
    const size_t rowBase = (size_t)blockIdx.y * 128;
    const size_t colBase = (size_t)nb * 256;

    float* scf = (float*)(smemc + SMEM_C_OFF); // [128][65] persistent c tile
    for (int i = tid; i < 128 * 65; i += 128) scf[i] = 0.f;

#if TC_OK
    if (tid < 32) { TCGEN05_ALLOC(tb, 256); TCGEN05_RELINQ(); }
    if (tid == 0) {
        MBARRIER_INIT(tb + 24, 1);   // done buf0
        MBARRIER_INIT(tb + 32, 1);   // done buf1
        MBARRIER_INIT(tb + 40, 1);   // MBF
    }
    __syncthreads();
    uint32_t tmem;
    asm volatile("ld.shared.b32 %0, [%1];" : "=r"(tmem) : "r"(tb));
    int cnt0 = 0, cnt1 = 0, mbfc = 0;
#else
    __syncthreads();
#endif

    for (int w = 0; w <= 96; w++) {
        const bool active = (z == 0) ? (w < 96) : (w >= 1);
        if (active) {
            const int t = (z == 0) ? w : (w - 1);
            const __half *A1, *B1;
            const __half *A2 = nullptr, *B2 = nullptr;
            const float *bias, *dec = nullptr, *dW0p = nullptr;
            __half *oh;
            int kA2 = 0;
            if (z == 0) {
                A1 = P.h0 + (size_t)t * BH;
                oh = P.h0 + (size_t)(t + 1) * BH;
                if (t < TENC) {
                    B1 = P.eU0;
                    A2 = P.x + (size_t)t * 1024 * 128;
                    B2 = P.eW0; kA2 = 128;
                    bias = P.eb0;
                } else {
                    B1 = P.dU0;
                    bias = P.db0; dec = P.dec + (t - TENC); dW0p = P.dW0;
                }
            } else {
                A1 = P.h1 + (size_t)t * BH;
                oh = P.h1 + (size_t)(t + 1) * BH;
                A2 = P.h0 + (size_t)(t + 1) * BH;
                kA2 = 512;
                if (t < TENC) { B1 = P.eU1; B2 = P.eW1; bias = P.eb1; }
                else          { B1 = P.dU1; B2 = P.dW1; bias = P.db1; }
            }
            const int kA1 = 512;
            const int ch1 = 8;
            const int nch = ch1 + (kA2 >> 6);

#if TC_OK
#define LOAD_CHUNK(cc) do { \
        const uint32_t _st = tb + 1024 + (uint32_t)((cc) & 1) * STAGE_BYTES; \
        const __half *_A, *_B; int _kA, _ko; \
        if ((cc) < ch1) { _A = A1; _B = B1; _kA = kA1; _ko = (cc) * 64; } \
        else { _A = A2; _B = B2; _kA = kA2; _ko = ((cc) - ch1) * 64; } \
        _Pragma("unroll") \
        for (int _i = 0; _i < 8; _i++) { \
            int _a = _i * 128 + tid; \
            int _r = _a >> 3, _s = _a & 7; \
            uint32_t _off = (uint32_t)(_r * 128 + _s * 16); \
            _off ^= (_off >> 3) & 0x70; \
            CP_ASYNC16(_st + _off, _A + (rowBase + _r) * (size_t)_kA + _ko + _s * 8); \
        } \
        _Pragma("unroll") \
        for (int _i = 0; _i < 16; _i++) { \
            int _a = _i * 128 + tid; \
            int _r = _a >> 3, _s = _a & 7; \
            uint32_t _off = (uint32_t)(_r * 128 + _s * 16); \
            _off ^= (_off >> 3) & 0x70; \
            CP_ASYNC16(_st + 16384 + _off, _B + (colBase + _r) * (size_t)_kA + _ko + _s * 8); \
        } \
        CP_COMMIT(); \
    } while (0)

            LOAD_CHUNK(0);
            LOAD_CHUNK(1);

            for (int c = 0; c < nch; c++) {
                if (c == nch - 1) CP_WAIT(0); else CP_WAIT(1);
                __syncthreads();
                if (tid < 32 && elect_one_pred()) {
                    const uint32_t st = tb + 1024 + (uint32_t)(c & 1) * STAGE_BYTES;
                    uint64_t ad = MAKE_SMEM_DESC(st);
                    uint64_t bd = MAKE_SMEM_DESC(st + 16384);
#pragma unroll
                    for (int j = 0; j < 4; j++) {
                        bool acc = !(c == 0 && j == 0);
                        mma_f16_ss(tmem,       ad + j * 2, bd + j * 2,        acc);
                        mma_f16_ss(tmem + 128, ad + j * 2, bd + 1024 + j * 2, acc);
                    }
                    TCGEN05_COMMIT(tb + 24 + (uint32_t)(c & 1) * 8);
                }
                int cn = (c & 1) ? cnt1 : cnt0;
                if (c + 2 < nch) {
                    MBARRIER_WAIT_PARITY(tb + 24 + (uint32_t)(c & 1) * 8, cn & 1);
                    LOAD_CHUNK(c + 2);
                }
                if (c & 1) cnt1++; else cnt0++;
            }
#undef LOAD_CHUNK

            if (tid < 32 && elect_one_pred()) TCGEN05_COMMIT(tb + 40);
            __syncthreads();
            MBARRIER_WAIT_PARITY(tb + 40, mbfc & 1);
            mbfc++;
            TCGEN05_FENCE_AFTER();

            // ---- epilogue: c stays in SMEM; h staged then coalesced writeback ----
            __half* shi = (__half*)(smemc + 1024);           // [128][66]
            const size_t row = rowBase + tid;
            const float dv = dec ? dec[row * SEG] : 0.f;

            for (int q = 0; q < 8; q++) {
                uint32_t dr[32];
                TCGEN05_LD_32X32B_X32(dr, tmem + q * 32);
                TCGEN05_WAIT_LD();
                const int nlb = ((q & 4) ? 32 : 0) + (q & 3) * 8;
#pragma unroll
                for (int jj = 0; jj < 8; jj++) {
                    int nl = nlb + jj;
                    int hg = nb * 64 + nl;
                    float zi = __uint_as_float(dr[jj * 4 + 0]) + bias[hg];
                    float zf = __uint_as_float(dr[jj * 4 + 1]) + bias[512 + hg];
                    float zg = __uint_as_float(dr[jj * 4 + 2]) + bias[1024 + hg];
                    float zo = __uint_as_float(dr[jj * 4 + 3]) + bias[1536 + hg];
                    if (dec) {
                        zi += dv * dW0p[hg];
                        zf += dv * dW0p[512 + hg];
                        zg += dv * dW0p[1024 + hg];
                        zo += dv * dW0p[1536 + hg];
                    }
                    float cn2, h;
                    lstm_gates(zi, zf, zg, zo, scf[tid * 65 + nl], cn2, h);
                    scf[tid * 65 + nl] = cn2;
                    shi[tid * 66 + nl] = __float2half(h);
                }
            }
            __syncthreads();
#pragma unroll 4
            for (int i = 0; i < 64; i++) {
                int idx = i * 128 + tid, r = idx >> 6, cc = idx & 63;
                oh[(rowBase + r) * Hdim + nb * 64 + cc] = shi[r * 66 + cc];
            }
#else
            // ---------- FFMA fallback (non-'a' pass; unused when 'a' cubin loads) ----------
            float* sA = (float*)(smemc + 1024);                // [32][132]
            float* sB = (float*)(smemc + 1024 + 16896);        // [32][68]
            const int tr = tid >> 3, tc8 = tid & 7;
            for (int pass = 0; pass < 4; pass++) {
                float acc[8][8];
#pragma unroll
                for (int r = 0; r < 8; r++)
#pragma unroll
                    for (int j = 0; j < 8; j++) acc[r][j] = 0.f;
                for (int part = 0; part < 2; part++) {
                    if (part == 1 && !A2) break;
                    const __half* Ap = part ? A2 : A1;
                    const __half* Bp = part ? B2 : B1;
                    const int kA = part ? kA2 : kA1;
                    for (int k0 = 0; k0 < kA; k0 += 32) {
                        __syncthreads();
#pragma unroll 4
                        for (int i = 0; i < 32; i++) {
                            int idx = i * 128 + tid, r = idx >> 5, kk = idx & 31;
                            sA[kk * 132 + r] = __half2float(Ap[(rowBase + r) * (size_t)kA + k0 + kk]);
                        }
#pragma unroll 2
                        for (int i = 0; i < 16; i++) {
                            int idx = i * 128 + tid, r = idx >> 5, kk = idx & 31;
                            sB[kk * 68 + r] = __half2float(Bp[(colBase + pass * 64 + r) * (size_t)kA + k0 + kk]);
                        }
                        __syncthreads();
#pragma unroll
                        for (int k = 0; k < 32; k++) {
                            float a[8], b[8];
#pragma unroll
                            for (int r = 0; r < 8; r++) a[r] = sA[k * 132 + tr * 8 + r];
#pragma unroll
                            for (int j = 0; j < 8; j++) b[j] = sB[k * 68 + tc8 * 8 + j];
#pragma unroll
                            for (int r = 0; r < 8; r++)
#pragma unroll
                                for (int j = 0; j < 8; j++) acc[r][j] += a[r] * b[j];
                        }
                    }
                }
                __syncthreads();
#pragma unroll
                for (int r = 0; r < 8; r++) {
                    int lr = tr * 8 + r;
                    size_t row = rowBase + lr;
                    float dvr = dec ? dec[row * SEG] : 0.f;
#pragma unroll
                    for (int q = 0; q < 2; q++) {
                        int nl = ((pass & 2) ? 32 : 0) + (pass & 1) * 16 + tc8 * 2 + q;
                        int hg = nb * 64 + nl;
                        float zi = acc[r][q * 4 + 0] + bias[hg];
                        float zf = acc[r][q * 4 + 1] + bias[512 + hg];
                        float zg = acc[r][q * 4 + 2] + bias[1024 + hg];
                        float zo = acc[r][q * 4 + 3] + bias[1536 + hg];
                        if (dec) {
                            zi += dvr * dW0p[hg];
                            zf += dvr * dW0p[512 + hg];
                            zg += dvr * dW0p[1024 + hg];
                            zo += dvr * dW0p[1536 + hg];
                        }
                        float cn2, h;
                        lstm_gates(zi, zf, zg, zo, scf[lr * 65 + nl], cn2, h);
                        scf[lr * 65 + nl] = cn2;
                        oh[row * Hdim + hg] = __float2half(h);
                    }
                }
                __syncthreads();
            }
#endif
        }

        // -------- grid-wide wave barrier (all 128 CTAs co-resident) --------
        __threadfence();
        __syncthreads();
        if (tid == 0) {
            atomicAdd(&g_bar, 1u);
            unsigned tgt = 128u * (unsigned)(w + 1), v;
            do {
                asm volatile("ld.acquire.gpu.u32 %0, [%1];" : "=r"(v) : "l"(&g_bar) : "memory");
            } while (v < tgt);
        }
        __syncthreads();
    }

#if TC_OK
    if (tid < 32) TCGEN05_DEALLOC(tmem, 256);
#endif
}

// ------------------- final dense -------------------
__global__ void __launch_bounds__(256) dense_kernel(
    const __half* __restrict__ hh, const float* __restrict__ W,
    const float* __restrict__ bb, float* __restrict__ out)
{
    int wid = (blockIdx.x * blockDim.x + threadIdx.x) >> 5;
    int lane = threadIdx.x & 31;
    if (wid >= Bsz * SEG) return;
    int b = wid / SEG, s = wid % SEG;
    size_t base = (size_t)(TENC + 1 + s) * BH + (size_t)b * Hdim;
    float sum = 0.f;
#pragma unroll 4
    for (int k = lane; k < Hdim; k += 32)
        sum += __half2float(hh[base + k]) * W[k];
#pragma unroll
    for (int o = 16; o > 0; o >>= 1) sum += __shfl_down_sync(0xffffffffu, sum, o);
    if (lane == 0) out[(size_t)b * SEG + s] = sum + bb[0];
}

// ------------------- host -------------------
extern "C" void kernel_launch(void* const* d_in, const int* in_sizes, int n_in,
                              void* d_out, int out_size)
{
    const float* x      = (const float*)d_in[0];
    const float* decin  = (const float*)d_in[1];
    const float* eW0    = (const float*)d_in[2];
    const float* eU0    = (const float*)d_in[3];
    const float* eb0    = (const float*)d_in[4];
    const float* eW1    = (const float*)d_in[5];
    const float* eU1    = (const float*)d_in[6];
    const float* eb1    = (const float*)d_in[7];
    const float* dW0    = (const float*)d_in[8];
    const float* dU0    = (const float*)d_in[9];
    const float* db0    = (const float*)d_in[10];
    const float* dW1    = (const float*)d_in[11];
    const float* dU1    = (const float*)d_in[12];
    const float* db1    = (const float*)d_in[13];
    const float* denseW = (const float*)d_in[14];
    const float* denseb = (const float*)d_in[15];
    float* out = (float*)d_out;

    cudaFuncSetAttribute(lstm_persist, cudaFuncAttributeMaxDynamicSharedMemorySize, SMEM_BYTES);

    Params P;
    cudaGetSymbolAddress((void**)&P.h0, g_h0);
    cudaGetSymbolAddress((void**)&P.h1, g_h1);
    cudaGetSymbolAddress((void**)&P.x, g_x);
    cudaGetSymbolAddress((void**)&P.eU0, g_eU0);
    cudaGetSymbolAddress((void**)&P.eU1, g_eU1);
    cudaGetSymbolAddress((void**)&P.dU0, g_dU0);
    cudaGetSymbolAddress((void**)&P.dU1, g_dU1);
    cudaGetSymbolAddress((void**)&P.eW1, g_eW1);
    cudaGetSymbolAddress((void**)&P.dW1, g_dW1);
    cudaGetSymbolAddress((void**)&P.eW0, g_eW0);
    P.eb0 = eb0; P.eb1 = eb1; P.db0 = db0; P.db1 = db1; P.dW0 = dW0; P.dec = decin;

    {
        size_t total = (size_t)6 * WK + 2048 * 128 + (size_t)65536 * 128;
        conv_all<<<(int)((total + 255) / 256), 256>>>(
            eU0, eU1, dU0, dU1, eW1, dW1, eW0, x,
            (__half*)P.eU0, (__half*)P.eU1, (__half*)P.dU0, (__half*)P.dU1,
            (__half*)P.eW1, (__half*)P.dW1, (__half*)P.eW0, (__half*)P.x);
    }
    zero_init<<<(BH + 255) / 256, 256>>>(P.h0, P.h1);

    lstm_persist<<<dim3(8, 8, 2), 128, SMEM_BYTES>>>(P);

    dense_kernel<<<(Bsz * SEG * 32) / 256, 256>>>(P.h1, denseW, denseb, out);
}